// round 15
// baseline (speedup 1.0000x reference)
#include <cuda_runtime.h>
#include <cuda_bf16.h>
#include <math.h>

#define BB 4
#define SS 2048
#define DD 1024
#define HH 16
#define DP 64
#define MM (BB*SS)
#define NROWS (BB*HH*SS)
#define NTILES 16              // 2048 / 128 k-tiles per attn row

static const long long OUT_ELEMS  = (long long)BB*SS*DD;
static const long long ATTN_ELEMS = (long long)BB*HH*(long long)SS*SS;

// Scratch (__device__ globals per allocation rules)
__device__ float g_Qh[BB*HH*SS*DP];
__device__ float g_Kh[BB*HH*SS*DP];
__device__ float g_Vh[BB*HH*SS*DP];
__device__ float g_ctx[BB*SS*DD];
__device__ float g_attn[BB*HH*(long long)SS*SS];
__device__ float g_pm[(long long)NROWS*NTILES];
__device__ float g_ps[(long long)NROWS*NTILES];
__device__ float g_rm[NROWS];
__device__ float g_rs[NROWS];

// ---------------------------------------------------------------------------
__device__ __forceinline__ unsigned f2tf(float x) {
    unsigned r;
    asm("cvt.rna.tf32.f32 %0, %1;" : "=r"(r) : "f"(x));
    return r;
}
__device__ __forceinline__ unsigned raw2tf(unsigned x) {
    return f2tf(__uint_as_float(x));
}

__device__ __forceinline__ void mma_tf32(float c[4], const unsigned a[4], const unsigned b[2]) {
    asm volatile(
        "mma.sync.aligned.m16n8k8.row.col.f32.tf32.tf32.f32 "
        "{%0,%1,%2,%3}, {%4,%5,%6,%7}, {%8,%9}, {%0,%1,%2,%3};"
        : "+f"(c[0]), "+f"(c[1]), "+f"(c[2]), "+f"(c[3])
        : "r"(a[0]), "r"(a[1]), "r"(a[2]), "r"(a[3]), "r"(b[0]), "r"(b[1]));
}

// ldmatrix x4 (b16 view of b32 quads) — fragment mapping verified in R5.
__device__ __forceinline__ void ldsm_x4(unsigned r[4], const unsigned* p) {
    unsigned addr = (unsigned)__cvta_generic_to_shared(p);
    asm volatile("ldmatrix.sync.aligned.m8n8.x4.shared.b16 {%0,%1,%2,%3}, [%4];"
                 : "=r"(r[0]), "=r"(r[1]), "=r"(r[2]), "=r"(r[3]) : "r"(addr));
}

__device__ __forceinline__ void cp_async16(unsigned* smem, const float* gmem) {
    unsigned s = (unsigned)__cvta_generic_to_shared(smem);
    asm volatile("cp.async.ca.shared.global [%0], [%1], 16;" :: "r"(s), "l"(gmem));
}
__device__ __forceinline__ void cp_commit() {
    asm volatile("cp.async.commit_group;");
}
template<int N>
__device__ __forceinline__ void cp_wait() {
    asm volatile("cp.async.wait_group %0;" :: "n"(N));
}

// ---------------------------------------------------------------------------
// Pipelined TF32 tensor-core GEMM:  C = alpha * A @ op(B) + bias
//  BT=false: B [K,N] row-major, Bs[k][n], scalar B fragments.
//  BT=true : B [N,K] row-major, Bs[n][k], ldmatrix B fragments (NT even).
//  SPLIT: 0 = C[z*sC + r*N+c]; 1 = head-split [b,h,s,d]; 2 = merged ctx;
//         3 = QK mode: v = alpha*acc + mask*(-1e9) stored raw + partial
//             softmax stats to g_pm/g_ps (mask2 != nullptr, z = bh).
// ---------------------------------------------------------------------------
template<int BM, int BN, int BK, int WM, int WN, bool BT, int SPLIT, int THREADS>
__global__ __launch_bounds__(THREADS, 2)
void mma_gemm_kernel(const float* __restrict__ A,
                     const float* __restrict__ Bm,
                     const float* __restrict__ bias,
                     const float* __restrict__ mask2,
                     float* __restrict__ C,
                     int M, int N, int K,
                     long long sA, long long sB, long long sC,
                     float alpha)
{
    constexpr int AP  = BK + 4;
    constexpr int BP  = BN + 4;
    constexpr int BP2 = BK + 4;
    constexpr int ASZ = BM * AP;
    constexpr int BSZ = BT ? (BN * BP2) : (BK * BP);
    __shared__ __align__(16) unsigned As[2 * ASZ];
    __shared__ __align__(16) unsigned Bs[2 * BSZ];

    const int tid  = threadIdx.x;
    const int lane = tid & 31;
    const int warp = tid >> 5;
    constexpr int WN_CNT = BN / WN;
    const int wm = warp / WN_CNT;
    const int wn = warp % WN_CNT;
    const int row0 = blockIdx.y * BM;
    const int col0 = blockIdx.x * BN;
    const int z    = blockIdx.z;

    A  += (long long)z * sA;
    Bm += (long long)z * sB;

    constexpr int MT = WM / 16;
    constexpr int NT = WN / 8;
    float cfr[MT][NT][4];
#pragma unroll
    for (int mt = 0; mt < MT; mt++)
#pragma unroll
        for (int nt = 0; nt < NT; nt++)
#pragma unroll
            for (int i = 0; i < 4; i++) cfr[mt][nt][i] = 0.0f;

    const int grp  = lane >> 3, rrw = lane & 7;
    const int a_ro = (grp & 1) * 8 + rrw;
    const int a_ko = (grp >> 1) * 4;
    const int b_no = (grp >> 1) * 8 + rrw;
    const int b_ko = (grp & 1) * 4;

    auto load_tiles = [&](int buf, int k0) {
        unsigned* Ad = As + buf * ASZ;
        unsigned* Bd = Bs + buf * BSZ;
#pragma unroll
        for (int i = 0; i < (BM * (BK / 4)) / THREADS; i++) {
            int idx = tid + i * THREADS;
            int r   = idx / (BK / 4);
            int kq  = (idx % (BK / 4)) * 4;
            cp_async16(&Ad[r * AP + kq], A + (long long)(row0 + r) * K + k0 + kq);
        }
        if (BT) {
#pragma unroll
            for (int i = 0; i < (BN * (BK / 4)) / THREADS; i++) {
                int idx = tid + i * THREADS;
                int n   = idx / (BK / 4);
                int kq  = (idx % (BK / 4)) * 4;
                cp_async16(&Bd[n * BP2 + kq], Bm + (long long)(col0 + n) * K + k0 + kq);
            }
        } else {
#pragma unroll
            for (int i = 0; i < (BK * (BN / 4)) / THREADS; i++) {
                int idx = tid + i * THREADS;
                int kk  = idx / (BN / 4);
                int nq  = (idx % (BN / 4)) * 4;
                cp_async16(&Bd[kk * BP + nq], Bm + (long long)(k0 + kk) * N + col0 + nq);
            }
        }
        cp_commit();
    };

    const int NK = K / BK;
    load_tiles(0, 0);

    for (int it = 0; it < NK; it++) {
        if (it + 1 < NK) {
            load_tiles((it + 1) & 1, (it + 1) * BK);
            cp_wait<1>();
        } else {
            cp_wait<0>();
        }
        __syncthreads();

        const unsigned* Ab = As + (it & 1) * ASZ;
        const unsigned* Bb = Bs + (it & 1) * BSZ;
#pragma unroll
        for (int ks = 0; ks < BK / 8; ks++) {
            unsigned af[MT][4];
            unsigned bf[NT][2];
#pragma unroll
            for (int mt = 0; mt < MT; mt++) {
                ldsm_x4(af[mt], &Ab[(wm * WM + mt * 16 + a_ro) * AP + ks * 8 + a_ko]);
#pragma unroll
                for (int j = 0; j < 4; j++) af[mt][j] = raw2tf(af[mt][j]);
            }
            if (BT) {
#pragma unroll
                for (int np = 0; np < NT / 2; np++) {
                    unsigned qv[4];
                    ldsm_x4(qv, &Bb[(wn * WN + np * 16 + b_no) * BP2 + ks * 8 + b_ko]);
                    bf[np * 2 + 0][0] = raw2tf(qv[0]); bf[np * 2 + 0][1] = raw2tf(qv[1]);
                    bf[np * 2 + 1][0] = raw2tf(qv[2]); bf[np * 2 + 1][1] = raw2tf(qv[3]);
                }
            } else {
                const int kb = ks * 8 + (lane & 3);
#pragma unroll
                for (int nt = 0; nt < NT; nt++) {
                    int cc = wn * WN + nt * 8 + (lane >> 2);
                    bf[nt][0] = raw2tf(Bb[kb * BP + cc]);
                    bf[nt][1] = raw2tf(Bb[(kb + 4) * BP + cc]);
                }
            }
#pragma unroll
            for (int mt = 0; mt < MT; mt++)
#pragma unroll
                for (int nt = 0; nt < NT; nt++)
                    mma_tf32(cfr[mt][nt], af[mt], bf[nt]);
        }
        __syncthreads();
    }

    // ======================= epilogue =======================
    if (SPLIT == 3) {
        // v = alpha*acc + mask*(-1e9), in place
#pragma unroll
        for (int mt = 0; mt < MT; mt++)
#pragma unroll
            for (int nt = 0; nt < NT; nt++)
#pragma unroll
                for (int i = 0; i < 4; i++) {
                    int r = row0 + wm * WM + mt * 16 + (lane >> 2) + ((i >= 2) ? 8 : 0);
                    int c = col0 + wn * WN + nt * 8 + (lane & 3) * 2 + (i & 1);
                    float mk = mask2[(long long)r * SS + c];
                    cfr[mt][nt][i] = fmaf(mk, -1e9f, cfr[mt][nt][i] * alpha);
                }
        // per-(row, warp-32-col) stats, then cross-warp reduce
        float* redm = (float*)As;          // 128*4 floats
        float* reds = redm + BM * WN_CNT;  // 128*4 floats
#pragma unroll
        for (int mt = 0; mt < MT; mt++) {
#pragma unroll
            for (int hf = 0; hf < 2; hf++) {
                float m0 = -INFINITY;
#pragma unroll
                for (int nt = 0; nt < NT; nt++) {
                    m0 = fmaxf(m0, cfr[mt][nt][hf * 2 + 0]);
                    m0 = fmaxf(m0, cfr[mt][nt][hf * 2 + 1]);
                }
                m0 = fmaxf(m0, __shfl_xor_sync(0xffffffffu, m0, 1));
                m0 = fmaxf(m0, __shfl_xor_sync(0xffffffffu, m0, 2));
                float s0 = 0.0f;
#pragma unroll
                for (int nt = 0; nt < NT; nt++) {
                    s0 += __expf(cfr[mt][nt][hf * 2 + 0] - m0);
                    s0 += __expf(cfr[mt][nt][hf * 2 + 1] - m0);
                }
                s0 += __shfl_xor_sync(0xffffffffu, s0, 1);
                s0 += __shfl_xor_sync(0xffffffffu, s0, 2);
                if ((lane & 3) == 0) {
                    int rl = wm * WM + mt * 16 + (lane >> 2) + hf * 8;
                    redm[rl * WN_CNT + wn] = m0;
                    reds[rl * WN_CNT + wn] = s0;
                }
            }
        }
        __syncthreads();
        if (tid < BM) {
            float m = -INFINITY;
#pragma unroll
            for (int w = 0; w < WN_CNT; w++) m = fmaxf(m, redm[tid * WN_CNT + w]);
            float s = 0.0f;
#pragma unroll
            for (int w = 0; w < WN_CNT; w++)
                s += reds[tid * WN_CNT + w] * __expf(redm[tid * WN_CNT + w] - m);
            long long rowg = (long long)z * SS + row0 + tid;
            g_pm[rowg * NTILES + blockIdx.x] = m;
            g_ps[rowg * NTILES + blockIdx.x] = s;
        }
        // store raw masked logits
#pragma unroll
        for (int mt = 0; mt < MT; mt++)
#pragma unroll
            for (int nt = 0; nt < NT; nt++)
#pragma unroll
                for (int i = 0; i < 4; i++) {
                    int r = row0 + wm * WM + mt * 16 + (lane >> 2) + ((i >= 2) ? 8 : 0);
                    int c = col0 + wn * WN + nt * 8 + (lane & 3) * 2 + (i & 1);
                    C[(long long)z * sC + (long long)r * N + c] = cfr[mt][nt][i];
                }
    } else {
#pragma unroll
        for (int mt = 0; mt < MT; mt++)
#pragma unroll
            for (int nt = 0; nt < NT; nt++)
#pragma unroll
                for (int i = 0; i < 4; i++) {
                    int r = row0 + wm * WM + mt * 16 + (lane >> 2) + ((i >= 2) ? 8 : 0);
                    int c = col0 + wn * WN + nt * 8 + (lane & 3) * 2 + (i & 1);
                    float v = cfr[mt][nt][i] * alpha + (bias ? bias[c] : 0.0f);
                    if (SPLIT == 0) {
                        C[(long long)z * sC + (long long)r * N + c] = v;
                    } else if (SPLIT == 1) {
                        int b = r / SS, s = r % SS;
                        int h = c / DP, d = c % DP;
                        C[(((long long)b * HH + h) * SS + s) * DP + d] = v;
                    } else {
                        int b = z / HH, h = z % HH;
                        C[((long long)b * SS + r) * DD + h * DP + c] = v;
                    }
                }
    }
}

// ---------------------------------------------------------------------------
// Reduce partial stats -> per-row (max, 1/sum)
// ---------------------------------------------------------------------------
__global__ __launch_bounds__(256)
void stats_kernel()
{
    int row = blockIdx.x * 256 + threadIdx.x;
    if (row >= NROWS) return;
    const float* pm = g_pm + (long long)row * NTILES;
    const float* ps = g_ps + (long long)row * NTILES;
    float m = -INFINITY;
#pragma unroll
    for (int i = 0; i < NTILES; i++) m = fmaxf(m, pm[i]);
    float S = 0.0f;
#pragma unroll
    for (int i = 0; i < NTILES; i++) S += ps[i] * __expf(pm[i] - m);
    g_rm[row] = m;
    g_rs[row] = 1.0f / S;
}

// ---------------------------------------------------------------------------
// Fused normalize + ctx:  attn = exp(raw - m) * rinv (written out), and
// ctx = attn @ V.  cp.async 2-stage pipeline over 32 k-chunks of 64.
// Grid: (16 q-tiles, 64 bh), 256 threads (8 warps: 4 wm x 2 wn, 32x32).
// ---------------------------------------------------------------------------
__global__ __launch_bounds__(256)
void ctx_fused_kernel(float* __restrict__ attn)
{
    constexpr int PS  = 68;
    constexpr int PSZ = 128 * PS;   // logits tile words
    constexpr int VSZ = 64 * PS;    // V tile words
    constexpr int STG = PSZ + VSZ;  // per stage
    extern __shared__ unsigned dynsm[];
    float* sm_m    = (float*)(dynsm + 2 * STG);
    float* sm_rinv = sm_m + 128;

    const int tid  = threadIdx.x;
    const int lane = tid & 31;
    const int warp = tid >> 5;
    const int wm = warp >> 1;       // 0..3
    const int wn = warp & 1;        // 0..1
    const int bh = blockIdx.y;
    const int b  = bh / HH;
    const int h  = bh % HH;
    const int q0 = blockIdx.x * 128;

    if (tid < 128) {
        long long rowg = (long long)bh * SS + q0 + tid;
        sm_m[tid]    = g_rm[rowg];
        sm_rinv[tid] = g_rs[rowg];
    }

    float* Ab = attn + ((long long)bh * SS + q0) * SS;
    const float* Vb = g_Vh + (long long)bh * SS * DP;

    auto load_chunk = [&](int buf, int k0) {
        unsigned* Ps = dynsm + buf * STG;
        unsigned* Vs = Ps + PSZ;
#pragma unroll
        for (int i = 0; i < 8; i++) {
            int idx = tid + i * 256;
            int r   = idx >> 4;
            int c4  = (idx & 15) * 4;
            cp_async16(&Ps[r * PS + c4], Ab + (long long)r * SS + k0 + c4);
        }
#pragma unroll
        for (int i = 0; i < 4; i++) {
            int idx = tid + i * 256;
            int kk  = idx >> 4;
            int n4  = (idx & 15) * 4;
            cp_async16(&Vs[kk * PS + n4], Vb + (long long)(k0 + kk) * DP + n4);
        }
        cp_commit();
    };

    float acc[2][4][4];
#pragma unroll
    for (int mt = 0; mt < 2; mt++)
#pragma unroll
        for (int nt = 0; nt < 4; nt++)
#pragma unroll
            for (int i = 0; i < 4; i++) acc[mt][nt][i] = 0.0f;

    const int grp  = lane >> 3, rrw = lane & 7;
    const int a_ro = (grp & 1) * 8 + rrw;
    const int a_ko = (grp >> 1) * 4;

    load_chunk(0, 0);

    for (int it = 0; it < SS / 64; it++) {
        if (it + 1 < SS / 64) {
            load_chunk((it + 1) & 1, (it + 1) * 64);
            cp_wait<1>();
        } else {
            cp_wait<0>();
        }
        __syncthreads();

        unsigned* Ps = dynsm + (it & 1) * STG;
        unsigned* Vs = Ps + PSZ;
        const int k0 = it * 64;

        // exp + normalize: write attn out, leave tf32 bits in smem
#pragma unroll
        for (int i = 0; i < 8; i++) {
            int idx = tid + i * 256;
            int r   = idx >> 4;
            int c4  = (idx & 15) * 4;
            float4 v = *(float4*)&Ps[r * PS + c4];
            float m = sm_m[r], rv = sm_rinv[r];
            v.x = __expf(v.x - m) * rv;
            v.y = __expf(v.y - m) * rv;
            v.z = __expf(v.z - m) * rv;
            v.w = __expf(v.w - m) * rv;
            *(float4*)(Ab + (long long)r * SS + k0 + c4) = v;
            uint4 u;
            u.x = f2tf(v.x); u.y = f2tf(v.y); u.z = f2tf(v.z); u.w = f2tf(v.w);
            *(uint4*)&Ps[r * PS + c4] = u;
        }
        __syncthreads();

        // MMA: A = Ps (tf32 bits) via ldmatrix, B = Vs raw fp32 scalar frags
#pragma unroll
        for (int ks = 0; ks < 8; ks++) {
            unsigned af[2][4];
            unsigned bf[4][2];
#pragma unroll
            for (int mt = 0; mt < 2; mt++)
                ldsm_x4(af[mt], &Ps[(wm * 32 + mt * 16 + a_ro) * PS + ks * 8 + a_ko]);
            const int kb = ks * 8 + (lane & 3);
#pragma unroll
            for (int nt = 0; nt < 4; nt++) {
                int cc = wn * 32 + nt * 8 + (lane >> 2);
                bf[nt][0] = raw2tf(Vs[kb * PS + cc]);
                bf[nt][1] = raw2tf(Vs[(kb + 4) * PS + cc]);
            }
#pragma unroll
            for (int mt = 0; mt < 2; mt++)
#pragma unroll
                for (int nt = 0; nt < 4; nt++)
                    mma_tf32(acc[mt][nt], af[mt], bf[nt]);
        }
        __syncthreads();
    }

    // store ctx merged [b,s,D]
#pragma unroll
    for (int mt = 0; mt < 2; mt++)
#pragma unroll
        for (int nt = 0; nt < 4; nt++)
#pragma unroll
            for (int i = 0; i < 4; i++) {
                int s = q0 + wm * 32 + mt * 16 + (lane >> 2) + ((i >= 2) ? 8 : 0);
                int d = wn * 32 + nt * 8 + (lane & 3) * 2 + (i & 1);
                g_ctx[((long long)b * SS + s) * DD + h * DP + d] = acc[mt][nt][i];
            }
}

// ---------------------------------------------------------------------------
extern "C" void kernel_launch(void* const* d_in, const int* in_sizes, int n_in,
                              void* d_out, int out_size)
{
    const float* q    = (const float*)d_in[0];
    const float* k    = (const float*)d_in[1];
    const float* v    = (const float*)d_in[2];
    const float* mask = (const float*)d_in[3];
    const float* Wq   = (const float*)d_in[4];
    const float* bq   = (const float*)d_in[5];
    const float* Wk   = (const float*)d_in[6];
    const float* bk   = (const float*)d_in[7];
    const float* Wv   = (const float*)d_in[8];
    const float* bv   = (const float*)d_in[9];
    const float* Wo   = (const float*)d_in[10];
    const float* bo   = (const float*)d_in[11];

    float* outp  = (float*)d_out;
    float* attnp = nullptr;
    if ((long long)out_size >= OUT_ELEMS + ATTN_ELEMS) {
        attnp = outp + OUT_ELEMS;
    } else {
        void* sym = nullptr;
        cudaGetSymbolAddress(&sym, g_attn);
        attnp = (float*)sym;
    }

    float* Qh = nullptr;  cudaGetSymbolAddress((void**)&Qh,  g_Qh);
    float* Kh = nullptr;  cudaGetSymbolAddress((void**)&Kh,  g_Kh);
    float* Vh = nullptr;  cudaGetSymbolAddress((void**)&Vh,  g_Vh);
    float* ctx = nullptr; cudaGetSymbolAddress((void**)&ctx, g_ctx);

    // --- Q/K/V projections (head-split outputs) ---
    mma_gemm_kernel<128,128,16,64,32,false,1,256><<<dim3(8,64,1), 256>>>(
        q, Wq, bq, nullptr, Qh, MM, DD, DD, 0, 0, 0, 1.0f);
    mma_gemm_kernel<128,128,16,64,32,false,1,256><<<dim3(8,64,1), 256>>>(
        k, Wk, bk, nullptr, Kh, MM, DD, DD, 0, 0, 0, 1.0f);
    mma_gemm_kernel<128,128,16,64,32,false,1,256><<<dim3(8,64,1), 256>>>(
        v, Wv, bv, nullptr, Vh, MM, DD, DD, 0, 0, 0, 1.0f);

    // --- QK^T + mask + scale + partial softmax stats (raw logits out) ---
    mma_gemm_kernel<128,128,16,64,32,true,3,256><<<dim3(16,16,BB*HH), 256>>>(
        Qh, Kh, nullptr, mask, attnp, SS, SS, DP,
        (long long)SS*DP, (long long)SS*DP, (long long)SS*SS, 0.125f);

    // --- finalize row stats ---
    stats_kernel<<<(NROWS + 255)/256, 256>>>();

    // --- fused normalize (attn out) + ctx = attn @ V ---
    {
        int smem = (2 * (128*68 + 64*68) + 256) * 4;   // ~105.5 KB
        cudaFuncSetAttribute(ctx_fused_kernel,
            cudaFuncAttributeMaxDynamicSharedMemorySize, smem);
        ctx_fused_kernel<<<dim3(16, BB*HH), 256, smem>>>(attnp);
    }

    // --- output projection ---
    mma_gemm_kernel<128,128,16,64,32,false,0,256><<<dim3(8,64,1), 256>>>(
        ctx, Wo, bo, nullptr, outp, MM, DD, DD, 0, 0, 0, 1.0f);
}